// round 14
// baseline (speedup 1.0000x reference)
#include <cuda_runtime.h>
#include <cuda_fp16.h>
#include <cstdint>

// LSTM (B=16384, T=28, I=28, H=64) + classifier via warp-level mma.sync fp16.
// One CTA = 128 batches, 1024 threads = 32 warps = 4 M-chunks x 8 N-groups,
// warp tile m32 x n32 (square tiles minimize LDSM read amplification: SMEM
// traffic 480->384 KB/step; L1 port was 67% = binding pipe in R13).
// B rows gate-interleaved in tile pairs (unit j: even n8 tile [i,f], odd
// [g,o]) so each thread gets all 4 gates of its units from the D fragment.
// Bias rides in the GEMM (A col 28 = 1.0, B col 28 = bih+bhh).
// Activations: tanh.approx (sigmoid = 0.5*tanh(x/2)+0.5).
// Sync: per-M-group named barriers (8 warps, 256 threads) -- all deps
// (x rows, h cols for those rows) are group-local.

#define NTHR    1024
#define BT      128
#define TSTEPS  28
#define IDIM    28
#define HDIM    64

// SMEM layout (bytes). A panels: 128 rows x 64 fp16 cols (128B rows, SW128).
// B panels: 256 rows x 64 fp16 cols.
#define OFF_A0    0
#define OFF_A1    16384
#define OFF_B0    32768
#define OFF_B1    65536
#define OFF_HST   98304                  // 128 x 65 floats
#define SMEM_SZ   (OFF_HST + 128*65*4)   // 131584

#define SWZ(b) ((b) ^ (((b) >> 3) & 0x70))

static __device__ __forceinline__ uint32_t smem_u32(const void* p) {
    uint32_t a;
    asm("{ .reg .u64 t; cvta.to.shared.u64 t, %1; cvt.u32.u64 %0, t; }" : "=r"(a) : "l"(p));
    return a;
}
#define GROUP_BAR(ID)                                                        \
    asm volatile("bar.sync %0, 256;" :: "r"(ID) : "memory")
#define LDSM4(R0, R1, R2, R3, A)                                             \
    asm volatile("ldmatrix.sync.aligned.m8n8.x4.shared.b16 {%0,%1,%2,%3}, [%4];" \
                 : "=r"(R0), "=r"(R1), "=r"(R2), "=r"(R3) : "r"(A))
#define MMA16816(D, A0, A1, A2, A3, B0, B1)                                  \
    asm volatile("mma.sync.aligned.m16n8k16.row.col.f32.f16.f16.f32 "        \
                 "{%0,%1,%2,%3}, {%4,%5,%6,%7}, {%8,%9}, {%0,%1,%2,%3};"     \
                 : "+f"((D)[0]), "+f"((D)[1]), "+f"((D)[2]), "+f"((D)[3])    \
                 : "r"(A0), "r"(A1), "r"(A2), "r"(A3), "r"(B0), "r"(B1))

static __device__ __forceinline__ float tanhap(float v) {
    float r; asm("tanh.approx.f32 %0, %1;" : "=f"(r) : "f"(v)); return r;
}
static __device__ __forceinline__ float sigap(float v) {
    return fmaf(0.5f, tanhap(0.5f * v), 0.5f);
}

__global__ void __launch_bounds__(NTHR, 1)
lstm_mma_kernel(const float* __restrict__ x,
                const float* __restrict__ Wih,   // [256,28]
                const float* __restrict__ Whh,   // [256,64]
                const float* __restrict__ bih,
                const float* __restrict__ bhh,
                const float* __restrict__ Wcls,  // [10,64]
                const float* __restrict__ bcls,  // [10]
                float* __restrict__ out)         // [B,10]
{
    extern __shared__ char smem[];
    const uint32_t sb = smem_u32(smem);
    const int tid  = threadIdx.x;
    const int wid  = tid >> 5;
    const int lane = tid & 31;
    const int mc   = wid >> 3;           // M-chunk (32 batch rows)
    const int ng   = wid & 7;            // N-group (32 gate rows, units 8ng..+8)
    const int gtid = tid & 255;          // thread id within M-group
    const int barid = mc + 1;            // named barrier ids 1..4

    // ---- zero A panels (covers pads + initial h = 0) --------------------
    for (int i = tid; i < 2 * 16384 / 16; i += NTHR)
        ((uint4*)(smem + OFF_A0))[i] = make_uint4(0, 0, 0, 0);

    // ---- B fill (single fp16), tile-pair gate packing -------------------
    // unit j, gate g (0=i,1=f,2=g,3=o) -> B row
    //   n = (j>>4)*64 + ((j>>2)&3)*16 + (g>>1)*8 + (j&3)*2 + (g&1)
    // k: 0..27 = Wih, 28 = bias, 29..31 = 0, 32..95 = Whh.
    for (int idx = tid; idx < 256 * 96; idx += NTHR) {
        int orow = idx / 96, k = idx % 96;   // orow = g*64 + j (torch order)
        int g = orow >> 6, j = orow & 63;
        float w = 0.0f;
        if (k < IDIM)       w = Wih[orow * IDIM + k];
        else if (k == IDIM) w = bih[orow] + bhh[orow];
        else if (k >= 32)   w = Whh[orow * HDIM + (k - 32)];
        int n = ((j >> 4) << 6) + (((j >> 2) & 3) << 4) + ((g >> 1) << 3)
              + ((j & 3) << 1) + (g & 1);
        int p  = k >> 6, kl = k & 63;
        uint32_t sw = SWZ((uint32_t)(n * 128 + kl * 2));
        *(uint16_t*)(smem + (p ? OFF_B1 : OFF_B0) + sw) =
            __half_as_ushort(__float2half_rn(w));
    }
    // zero unused cols of B panel1 (kl 32..63)
    for (int idx = tid; idx < 256 * 32; idx += NTHR) {
        int n = idx >> 5, kl = 32 + (idx & 31);
        uint32_t sw = SWZ((uint32_t)(n * 128 + kl * 2));
        *(uint16_t*)(smem + OFF_B1 + sw) = 0;
    }
    // A col 28 = 1.0 for all rows (bias multiplier)
    if (tid < BT) {
        uint32_t sw = SWZ((uint32_t)(tid * 128 + IDIM * 2));
        *(uint16_t*)(smem + OFF_A0 + sw) = (uint16_t)0x3C00;
    }

    // ---- group-local x mapping (t-invariant) + prefetch x_0 -------------
    // group loads its 32 rows: 32*28 = 896 elems, 256 threads -> <=4 each
    const float* __restrict__ xb = x + (size_t)blockIdx.x * BT * TSTEPS * IDIM;
    int xoff[4], xsw[4];
#pragma unroll
    for (int i = 0; i < 4; i++) {
        int idx = gtid + i * 256;          // 0..1023; valid < 896
        int brow = idx / IDIM, k = idx % IDIM;
        if (idx < 896) {
            xoff[i] = (mc * 32 + brow) * (TSTEPS * IDIM) + k;
            xsw[i]  = (int)SWZ((uint32_t)((mc * 32 + brow) * 128 + k * 2));
        } else { xoff[i] = -1; xsw[i] = 0; }
    }
    float xr[4];
#pragma unroll
    for (int i = 0; i < 4; i++) xr[i] = (xoff[i] >= 0) ? xb[xoff[i]] : 0.0f;

    // ---- per-thread GEMM/epilogue constants -----------------------------
    const int arow0  = mc * 32 + (lane & 15);        // + 16*mi
    const int achunk = (lane >> 4) * 16;
    const int brow_l = ((lane >> 4) << 3) + (lane & 7);  // + 32*ng + 16*bt
    const int bchunk = ((lane >> 3) & 1) * 16;
    const int q      = lane & 3;                 // unit-within-pair
    const int rbase  = mc * 32 + (lane >> 2);    // + 16*mi + 8*rr

    float cs[8];                                 // [mi][tp][rr]
#pragma unroll
    for (int m = 0; m < 8; m++) cs[m] = 0.0f;

    float* hst = (float*)(smem + OFF_HST);       // classifier staging

    __syncthreads();      // B, A-init visible

    for (int t = 0; t < TSTEPS; ++t) {
        // ---- write x_t into A panel0 cols 0..27 (group rows only) -------
#pragma unroll
        for (int i = 0; i < 4; i++) {
            if (xoff[i] >= 0) {
                *(uint16_t*)(smem + OFF_A0 + xsw[i]) =
                    __half_as_ushort(__float2half_rn(xr[i]));
            }
        }
        GROUP_BAR(barid);    // group's x_t + h_t writes visible to group

        // ---- GEMM: 6 k16 steps, m32 x n32 per warp ----------------------
        float d[2][4][4];
#pragma unroll
        for (int mi = 0; mi < 2; mi++)
#pragma unroll
            for (int nt = 0; nt < 4; nt++) {
                d[mi][nt][0] = 0.0f; d[mi][nt][1] = 0.0f;
                d[mi][nt][2] = 0.0f; d[mi][nt][3] = 0.0f;
            }
#pragma unroll
        for (int ks = 0; ks < 6; ks++) {
            const int p  = (ks < 4) ? 0 : 1;
            const int cb = (ks < 4) ? ks * 32 : (ks - 4) * 32;
            const uint32_t apan = sb + (p ? OFF_A1 : OFF_A0);
            const uint32_t bpan = sb + (p ? OFF_B1 : OFF_B0);
            uint32_t a0[4], a1[4];
            LDSM4(a0[0], a0[1], a0[2], a0[3],
                  apan + SWZ((uint32_t)(arow0 * 128 + cb + achunk)));
            LDSM4(a1[0], a1[1], a1[2], a1[3],
                  apan + SWZ((uint32_t)((arow0 + 16) * 128 + cb + achunk)));
#pragma unroll
            for (int bt = 0; bt < 2; bt++) {
                const int nb = ng * 32 + bt * 16;
                uint32_t bv[4];
                LDSM4(bv[0], bv[1], bv[2], bv[3],
                      bpan + SWZ((uint32_t)((nb + brow_l) * 128 + cb + bchunk)));
                MMA16816(d[0][2 * bt],     a0[0], a0[1], a0[2], a0[3], bv[0], bv[1]);
                MMA16816(d[0][2 * bt + 1], a0[0], a0[1], a0[2], a0[3], bv[2], bv[3]);
                MMA16816(d[1][2 * bt],     a1[0], a1[1], a1[2], a1[3], bv[0], bv[1]);
                MMA16816(d[1][2 * bt + 1], a1[0], a1[1], a1[2], a1[3], bv[2], bv[3]);
            }
        }
        GROUP_BAR(barid);    // group's A reads done before h/x overwrite

        // ---- prefetch x_{t+1} (overlaps epilogue) -----------------------
        if (t < TSTEPS - 1) {
#pragma unroll
            for (int i = 0; i < 4; i++)
                if (xoff[i] >= 0) xr[i] = xb[xoff[i] + (t + 1) * IDIM];
        }

        // ---- epilogue: tile pair tp -> unit j = 8ng+4tp+q; no shfl ------
#pragma unroll
        for (int mi = 0; mi < 2; mi++)
#pragma unroll
            for (int tp = 0; tp < 2; tp++) {
                const int j = 8 * ng + 4 * tp + q;
                const int bytecol = (j < 32) ? (64 + 2 * j) : (2 * j - 64);
                const uint32_t apan_h = sb + ((j < 32) ? OFF_A0 : OFF_A1);
#pragma unroll
                for (int rr = 0; rr < 2; rr++) {
                    float gi = d[mi][2 * tp][2 * rr + 0];
                    float gf = d[mi][2 * tp][2 * rr + 1];
                    float gg = d[mi][2 * tp + 1][2 * rr + 0];
                    float go = d[mi][2 * tp + 1][2 * rr + 1];
                    float iv = sigap(gi), fv = sigap(gf);
                    float gv = tanhap(gg), ov = sigap(go);
                    const int m = mi * 4 + tp * 2 + rr;
                    float c = fv * cs[m] + iv * gv;
                    cs[m] = c;
                    float h = ov * tanhap(c);
                    const int b = rbase + 16 * mi + 8 * rr;
                    const uint32_t sw = SWZ((uint32_t)(b * 128 + bytecol));
                    *(uint16_t*)((char*)smem + (apan_h - sb) + sw) =
                        __half_as_ushort(__float2half_rn(h));
                    if (t == TSTEPS - 1) hst[b * 65 + j] = h;
                }
            }
    }
    __syncthreads();         // all groups finished; hst complete

    // ---- classifier: out[b,cls] = b_cls + sum_j h[b,j]*Wcls[cls,j] ------
    const int bbase = blockIdx.x * BT;
    for (int idx = tid; idx < BT * 10; idx += NTHR) {
        int b = idx / 10, cls = idx % 10;
        float s = bcls[cls];
        const float* __restrict__ wc = Wcls + cls * HDIM;
#pragma unroll
        for (int j = 0; j < HDIM; j++) s += hst[b * 65 + j] * __ldg(&wc[j]);
        out[(size_t)(bbase + b) * 10 + cls] = s;
    }
}

extern "C" void kernel_launch(void* const* d_in, const int* in_sizes, int n_in,
                              void* d_out, int out_size) {
    const float* x    = (const float*)d_in[0];
    const float* Wih  = (const float*)d_in[1];
    const float* Whh  = (const float*)d_in[2];
    const float* bih  = (const float*)d_in[3];
    const float* bhh  = (const float*)d_in[4];
    const float* Wcls = (const float*)d_in[5];
    const float* bcls = (const float*)d_in[6];
    float* out = (float*)d_out;

    cudaFuncSetAttribute(lstm_mma_kernel,
                         cudaFuncAttributeMaxDynamicSharedMemorySize, SMEM_SZ);
    lstm_mma_kernel<<<16384 / BT, NTHR, SMEM_SZ>>>(x, Wih, Whh, bih, bhh,
                                                   Wcls, bcls, out);
}

// round 15
// speedup vs baseline: 1.0275x; 1.0275x over previous
#include <cuda_runtime.h>
#include <cuda_fp16.h>
#include <cstdint>

// LSTM (B=16384, T=28, I=28, H=64) + classifier via warp-level mma.sync fp16.
// One CTA = 128 batches, 1024 threads = 32 warps = 8 warp-QUADS; quad mw owns
// batch rows [16mw,16mw+16); warp nq (0..3) owns N-quarter (64 gate-rows).
// R13 tiling (m16 x n64 per warp -- best measured) + PING-PONG A buffers:
// GEMM t reads buf[t&1]; epilogue h-writes and x_{t+1} go to buf[(t+1)&1].
// WAR hazard gone structurally -> ONE 128-thread barrier per step (was two).
// B rows gate-interleaved in tile pairs (unit j: even n8 tile [i,f], odd
// [g,o]): D fragment hands each thread all 4 gates of its unit, no shfl.
// Bias rides in the GEMM (A col 28 = 1.0, B col 28 = bih+bhh).
// Activations: tanh.approx (sigmoid = 0.5*tanh(x/2)+0.5).

#define NTHR    1024
#define BT      128
#define TSTEPS  28
#define IDIM    28
#define HDIM    64

// SMEM layout (bytes). A: 2 buffers x 2 panels x (128 rows x 128B) = 64KB.
// B panels: 2 x (256 rows x 128B) = 64KB.
#define ABUF(buf)  ((buf) * 32768)           // + pan*16384
#define OFF_B0    65536
#define OFF_B1    98304
#define OFF_HST   131072                     // 128 x 65 floats
#define SMEM_SZ   (OFF_HST + 128*65*4)       // 164352

#define SWZ(b) ((b) ^ (((b) >> 3) & 0x70))

static __device__ __forceinline__ uint32_t smem_u32(const void* p) {
    uint32_t a;
    asm("{ .reg .u64 t; cvta.to.shared.u64 t, %1; cvt.u32.u64 %0, t; }" : "=r"(a) : "l"(p));
    return a;
}
#define QUAD_BAR(ID)                                                         \
    asm volatile("bar.sync %0, 128;" :: "r"(ID) : "memory")
#define LDSM4(R0, R1, R2, R3, A)                                             \
    asm volatile("ldmatrix.sync.aligned.m8n8.x4.shared.b16 {%0,%1,%2,%3}, [%4];" \
                 : "=r"(R0), "=r"(R1), "=r"(R2), "=r"(R3) : "r"(A))
#define MMA16816(D, A, B0, B1)                                               \
    asm volatile("mma.sync.aligned.m16n8k16.row.col.f32.f16.f16.f32 "        \
                 "{%0,%1,%2,%3}, {%4,%5,%6,%7}, {%8,%9}, {%0,%1,%2,%3};"     \
                 : "+f"((D)[0]), "+f"((D)[1]), "+f"((D)[2]), "+f"((D)[3])    \
                 : "r"((A)[0]), "r"((A)[1]), "r"((A)[2]), "r"((A)[3]),       \
                   "r"(B0), "r"(B1))

static __device__ __forceinline__ float tanhap(float v) {
    float r; asm("tanh.approx.f32 %0, %1;" : "=f"(r) : "f"(v)); return r;
}
static __device__ __forceinline__ float sigap(float v) {
    return fmaf(0.5f, tanhap(0.5f * v), 0.5f);
}

__global__ void __launch_bounds__(NTHR, 1)
lstm_mma_kernel(const float* __restrict__ x,
                const float* __restrict__ Wih,   // [256,28]
                const float* __restrict__ Whh,   // [256,64]
                const float* __restrict__ bih,
                const float* __restrict__ bhh,
                const float* __restrict__ Wcls,  // [10,64]
                const float* __restrict__ bcls,  // [10]
                float* __restrict__ out)         // [B,10]
{
    extern __shared__ char smem[];
    const uint32_t sb = smem_u32(smem);
    const int tid  = threadIdx.x;
    const int wid  = tid >> 5;
    const int lane = tid & 31;
    const int mw   = wid >> 2;           // quad id: 16-row batch chunk
    const int nq   = wid & 3;            // N quarter (64 gate-rows, 16 units)
    const int ptid = tid & 127;          // thread id within quad
    const int barid = mw + 1;            // named barrier (ids 1..8)

    // ---- zero all 4 A panels (pads + initial h = 0) ---------------------
    for (int i = tid; i < 65536 / 16; i += NTHR)
        ((uint4*)smem)[i] = make_uint4(0, 0, 0, 0);

    // ---- B fill (single fp16), tile-pair gate packing -------------------
    // unit j, gate g (0=i,1=f,2=g,3=o) -> B row
    //   n = (j>>4)*64 + ((j>>2)&3)*16 + (g>>1)*8 + (j&3)*2 + (g&1)
    // k: 0..27 = Wih, 28 = bias, 29..31 = 0, 32..95 = Whh.
    for (int idx = tid; idx < 256 * 96; idx += NTHR) {
        int orow = idx / 96, k = idx % 96;   // orow = g*64 + j (torch order)
        int g = orow >> 6, j = orow & 63;
        float w = 0.0f;
        if (k < IDIM)       w = Wih[orow * IDIM + k];
        else if (k == IDIM) w = bih[orow] + bhh[orow];
        else if (k >= 32)   w = Whh[orow * HDIM + (k - 32)];
        int n = ((j >> 4) << 6) + (((j >> 2) & 3) << 4) + ((g >> 1) << 3)
              + ((j & 3) << 1) + (g & 1);
        int p  = k >> 6, kl = k & 63;
        uint32_t sw = SWZ((uint32_t)(n * 128 + kl * 2));
        *(uint16_t*)(smem + (p ? OFF_B1 : OFF_B0) + sw) =
            __half_as_ushort(__float2half_rn(w));
    }
    // zero unused cols of B panel1 (kl 32..63)
    for (int idx = tid; idx < 256 * 32; idx += NTHR) {
        int n = idx >> 5, kl = 32 + (idx & 31);
        uint32_t sw = SWZ((uint32_t)(n * 128 + kl * 2));
        *(uint16_t*)(smem + OFF_B1 + sw) = 0;
    }
    // A col 28 = 1.0 in BOTH buffers' panel0 (bias multiplier)
    if (tid < BT) {
        uint32_t sw = SWZ((uint32_t)(tid * 128 + IDIM * 2));
        *(uint16_t*)(smem + ABUF(0) + sw) = (uint16_t)0x3C00;
        *(uint16_t*)(smem + ABUF(1) + sw) = (uint16_t)0x3C00;
    }

    // ---- quad-local x mapping (t-invariant) -----------------------------
    const float* __restrict__ xb = x + (size_t)blockIdx.x * BT * TSTEPS * IDIM;
    int xoff[4], xsw[4];
#pragma unroll
    for (int i = 0; i < 4; i++) {
        int idx = ptid + i * 128;          // 0..511; valid < 448
        int brow = idx / IDIM, k = idx % IDIM;
        if (idx < 448) {
            xoff[i] = (mw * 16 + brow) * (TSTEPS * IDIM) + k;
            xsw[i]  = (int)SWZ((uint32_t)((mw * 16 + brow) * 128 + k * 2));
        } else { xoff[i] = -1; xsw[i] = 0; }
    }
    // x_0 -> buf0 panel0
#pragma unroll
    for (int i = 0; i < 4; i++) {
        if (xoff[i] >= 0) {
            *(uint16_t*)(smem + ABUF(0) + xsw[i]) =
                __half_as_ushort(__float2half_rn(xb[xoff[i]]));
        }
    }

    // ---- per-thread GEMM/epilogue constants -----------------------------
    const int arow   = mw * 16 + (lane & 15);
    const int achunk = (lane >> 4) * 16;
    const int brow_l = ((lane >> 4) << 3) + (lane & 7);
    const int bchunk = ((lane >> 3) & 1) * 16;
    const int q      = lane & 3;                 // unit-within-pair
    const int r0     = mw * 16 + (lane >> 2);    // first owned batch row
    const int pan    = nq >> 1;                  // h panel for this quarter

    float cs[8];
#pragma unroll
    for (int m = 0; m < 8; m++) cs[m] = 0.0f;

    float* hst = (float*)(smem + OFF_HST);       // classifier staging

    __syncthreads();      // B, A-init, x_0 visible

    for (int t = 0; t < TSTEPS; ++t) {
        const uint32_t abuf_r = (uint32_t)ABUF(t & 1);        // GEMM source
        const uint32_t abuf_w = (uint32_t)ABUF((t + 1) & 1);  // epilogue dest
        if (t) QUAD_BAR(barid);   // h_{t}/x_t writes to abuf_r visible

        // ---- GEMM: 6 k16 steps x 4 tile-pairs ---------------------------
        float d[8][4];
#pragma unroll
        for (int m = 0; m < 8; m++) {
            d[m][0] = 0.0f; d[m][1] = 0.0f; d[m][2] = 0.0f; d[m][3] = 0.0f;
        }
#pragma unroll
        for (int ks = 0; ks < 6; ks++) {
            const int p  = (ks < 4) ? 0 : 1;
            const int cb = (ks < 4) ? ks * 32 : (ks - 4) * 32;
            const uint32_t aswz = SWZ((uint32_t)(arow * 128 + cb + achunk));
            uint32_t av[4];
            LDSM4(av[0], av[1], av[2], av[3],
                  sb + abuf_r + (p ? 16384u : 0u) + aswz);
#pragma unroll
            for (int g2 = 0; g2 < 4; g2++) {
                const int nb = nq * 64 + g2 * 16;
                const uint32_t bswz =
                    SWZ((uint32_t)((nb + brow_l) * 128 + cb + bchunk));
                uint32_t bv[4];
                LDSM4(bv[0], bv[1], bv[2], bv[3],
                      sb + (p ? OFF_B1 : OFF_B0) + bswz);
                MMA16816(d[2 * g2],     av, bv[0], bv[1]);
                MMA16816(d[2 * g2 + 1], av, bv[2], bv[3]);
            }
        }

        // ---- load x_{t+1} (latency hides under epilogue) ----------------
        float xr[4];
        if (t < TSTEPS - 1) {
#pragma unroll
            for (int i = 0; i < 4; i++)
                if (xoff[i] >= 0) xr[i] = xb[xoff[i] + (t + 1) * IDIM];
        }

        // ---- epilogue: tile pair tp -> unit j; h into abuf_w ------------
#pragma unroll
        for (int tp = 0; tp < 4; tp++) {
            const int j = 16 * nq + 4 * tp + q;
            const int bytecol = pan ? (2 * j - 64) : (64 + 2 * j);
            const uint32_t hdst = abuf_w + (pan ? 16384u : 0u);
#pragma unroll
            for (int rr = 0; rr < 2; rr++) {
                float gi = d[2 * tp][2 * rr + 0];
                float gf = d[2 * tp][2 * rr + 1];
                float gg = d[2 * tp + 1][2 * rr + 0];
                float go = d[2 * tp + 1][2 * rr + 1];
                float iv = sigap(gi), fv = sigap(gf);
                float gv = tanhap(gg), ov = sigap(go);
                const int m = tp * 2 + rr;
                float c = fv * cs[m] + iv * gv;
                cs[m] = c;
                float h = ov * tanhap(c);
                const int b = r0 + 8 * rr;
                const uint32_t sw = SWZ((uint32_t)(b * 128 + bytecol));
                *(uint16_t*)(smem + hdst + sw) =
                    __half_as_ushort(__float2half_rn(h));
                if (t == TSTEPS - 1) hst[b * 65 + j] = h;
            }
        }

        // ---- store x_{t+1} into abuf_w panel0 ---------------------------
        if (t < TSTEPS - 1) {
#pragma unroll
            for (int i = 0; i < 4; i++) {
                if (xoff[i] >= 0) {
                    *(uint16_t*)(smem + abuf_w + xsw[i]) =
                        __half_as_ushort(__float2half_rn(xr[i]));
                }
            }
        }
    }
    __syncthreads();         // all quads finished; hst complete

    // ---- classifier: out[b,cls] = b_cls + sum_j h[b,j]*Wcls[cls,j] ------
    const int bbase = blockIdx.x * BT;
    for (int idx = tid; idx < BT * 10; idx += NTHR) {
        int b = idx / 10, cls = idx % 10;
        float s = bcls[cls];
        const float* __restrict__ wc = Wcls + cls * HDIM;
#pragma unroll
        for (int j = 0; j < HDIM; j++) s += hst[b * 65 + j] * __ldg(&wc[j]);
        out[(size_t)(bbase + b) * 10 + cls] = s;
    }
}

extern "C" void kernel_launch(void* const* d_in, const int* in_sizes, int n_in,
                              void* d_out, int out_size) {
    const float* x    = (const float*)d_in[0];
    const float* Wih  = (const float*)d_in[1];
    const float* Whh  = (const float*)d_in[2];
    const float* bih  = (const float*)d_in[3];
    const float* bhh  = (const float*)d_in[4];
    const float* Wcls = (const float*)d_in[5];
    const float* bcls = (const float*)d_in[6];
    float* out = (float*)d_out;

    cudaFuncSetAttribute(lstm_mma_kernel,
                         cudaFuncAttributeMaxDynamicSharedMemorySize, SMEM_SZ);
    lstm_mma_kernel<<<16384 / BT, NTHR, SMEM_SZ>>>(x, Wih, Whh, bih, bhh,
                                                   Wcls, bcls, out);
}

// round 16
// speedup vs baseline: 1.0882x; 1.0590x over previous
#include <cuda_runtime.h>
#include <cuda_fp16.h>
#include <cstdint>

// LSTM (B=16384, T=28, I=28, H=64) + classifier via warp-level mma.sync fp16.
// One CTA = 128 batches, 1024 threads = 32 warps = 8 warp-QUADS; quad mw owns
// batch rows [16mw,16mw+16); warp nq (0..3) owns N-quarter (64 gate-rows).
// Ping-pong A buffers (GEMM t reads buf[t&1], h_{t+1}/x_{t+1} -> buf[~t&1]),
// ONE quad barrier per step. NEW: tile-pair software pipeline -- epilogue of
// pair tp-1 is interleaved with the B-LDSM/MMA stream of pair tp, so MUFU/
// FMA/STS overlap tensor+LDSM inside each warp (phases no longer sum).
// B rows gate-interleaved in tile pairs (unit j: even n8 tile [i,f], odd
// [g,o]): D fragment hands each thread all 4 gates of its unit, no shfl.
// Bias rides in the GEMM (A col 28 = 1.0, B col 28 = bih+bhh).
// Activations: tanh.approx (sigmoid = 0.5*tanh(x/2)+0.5).

#define NTHR    1024
#define BT      128
#define TSTEPS  28
#define IDIM    28
#define HDIM    64

// SMEM layout (bytes). A: 2 buffers x 2 panels x (128 rows x 128B) = 64KB.
// B panels: 2 x (256 rows x 128B) = 64KB.
#define ABUF(buf)  ((buf) * 32768)           // + pan*16384
#define OFF_B0    65536
#define OFF_B1    98304
#define OFF_HST   131072                     // 128 x 65 floats
#define SMEM_SZ   (OFF_HST + 128*65*4)       // 164352

#define SWZ(b) ((b) ^ (((b) >> 3) & 0x70))

static __device__ __forceinline__ uint32_t smem_u32(const void* p) {
    uint32_t a;
    asm("{ .reg .u64 t; cvta.to.shared.u64 t, %1; cvt.u32.u64 %0, t; }" : "=r"(a) : "l"(p));
    return a;
}
#define QUAD_BAR(ID)                                                         \
    asm volatile("bar.sync %0, 128;" :: "r"(ID) : "memory")
#define LDSM4(R0, R1, R2, R3, A)                                             \
    asm volatile("ldmatrix.sync.aligned.m8n8.x4.shared.b16 {%0,%1,%2,%3}, [%4];" \
                 : "=r"(R0), "=r"(R1), "=r"(R2), "=r"(R3) : "r"(A))
#define MMA16816(D, A, B0, B1)                                               \
    asm volatile("mma.sync.aligned.m16n8k16.row.col.f32.f16.f16.f32 "        \
                 "{%0,%1,%2,%3}, {%4,%5,%6,%7}, {%8,%9}, {%0,%1,%2,%3};"     \
                 : "+f"((D)[0]), "+f"((D)[1]), "+f"((D)[2]), "+f"((D)[3])    \
                 : "r"((A)[0]), "r"((A)[1]), "r"((A)[2]), "r"((A)[3]),       \
                   "r"(B0), "r"(B1))

static __device__ __forceinline__ float tanhap(float v) {
    float r; asm("tanh.approx.f32 %0, %1;" : "=f"(r) : "f"(v)); return r;
}
static __device__ __forceinline__ float sigap(float v) {
    return fmaf(0.5f, tanhap(0.5f * v), 0.5f);
}

__global__ void __launch_bounds__(NTHR, 1)
lstm_mma_kernel(const float* __restrict__ x,
                const float* __restrict__ Wih,   // [256,28]
                const float* __restrict__ Whh,   // [256,64]
                const float* __restrict__ bih,
                const float* __restrict__ bhh,
                const float* __restrict__ Wcls,  // [10,64]
                const float* __restrict__ bcls,  // [10]
                float* __restrict__ out)         // [B,10]
{
    extern __shared__ char smem[];
    const uint32_t sb = smem_u32(smem);
    const int tid  = threadIdx.x;
    const int wid  = tid >> 5;
    const int lane = tid & 31;
    const int mw   = wid >> 2;           // quad id: 16-row batch chunk
    const int nq   = wid & 3;            // N quarter (64 gate-rows, 16 units)
    const int ptid = tid & 127;          // thread id within quad
    const int barid = mw + 1;            // named barrier (ids 1..8)

    // ---- zero all 4 A panels (pads + initial h = 0) ---------------------
    for (int i = tid; i < 65536 / 16; i += NTHR)
        ((uint4*)smem)[i] = make_uint4(0, 0, 0, 0);

    // ---- B fill (single fp16), tile-pair gate packing -------------------
    // unit j, gate g (0=i,1=f,2=g,3=o) -> B row
    //   n = (j>>4)*64 + ((j>>2)&3)*16 + (g>>1)*8 + (j&3)*2 + (g&1)
    // k: 0..27 = Wih, 28 = bias, 29..31 = 0, 32..95 = Whh.
    for (int idx = tid; idx < 256 * 96; idx += NTHR) {
        int orow = idx / 96, k = idx % 96;   // orow = g*64 + j (torch order)
        int g = orow >> 6, j = orow & 63;
        float w = 0.0f;
        if (k < IDIM)       w = Wih[orow * IDIM + k];
        else if (k == IDIM) w = bih[orow] + bhh[orow];
        else if (k >= 32)   w = Whh[orow * HDIM + (k - 32)];
        int n = ((j >> 4) << 6) + (((j >> 2) & 3) << 4) + ((g >> 1) << 3)
              + ((j & 3) << 1) + (g & 1);
        int p  = k >> 6, kl = k & 63;
        uint32_t sw = SWZ((uint32_t)(n * 128 + kl * 2));
        *(uint16_t*)(smem + (p ? OFF_B1 : OFF_B0) + sw) =
            __half_as_ushort(__float2half_rn(w));
    }
    // zero unused cols of B panel1 (kl 32..63)
    for (int idx = tid; idx < 256 * 32; idx += NTHR) {
        int n = idx >> 5, kl = 32 + (idx & 31);
        uint32_t sw = SWZ((uint32_t)(n * 128 + kl * 2));
        *(uint16_t*)(smem + OFF_B1 + sw) = 0;
    }
    // A col 28 = 1.0 in BOTH buffers' panel0 (bias multiplier)
    if (tid < BT) {
        uint32_t sw = SWZ((uint32_t)(tid * 128 + IDIM * 2));
        *(uint16_t*)(smem + ABUF(0) + sw) = (uint16_t)0x3C00;
        *(uint16_t*)(smem + ABUF(1) + sw) = (uint16_t)0x3C00;
    }

    // ---- quad-local x mapping (t-invariant) -----------------------------
    const float* __restrict__ xb = x + (size_t)blockIdx.x * BT * TSTEPS * IDIM;
    int xoff[4];
#pragma unroll
    for (int i = 0; i < 4; i++) {
        int idx = ptid + i * 128;          // 0..511; valid < 448
        int brow = idx / IDIM, k = idx % IDIM;
        xoff[i] = (idx < 448) ? ((mw * 16 + brow) * (TSTEPS * IDIM) + k) : -1;
    }
    // x_0 -> buf0 panel0
#pragma unroll
    for (int i = 0; i < 4; i++) {
        if (xoff[i] >= 0) {
            int idx = ptid + i * 128;
            int brow = idx / IDIM, k = idx % IDIM;
            uint32_t sw = SWZ((uint32_t)((mw * 16 + brow) * 128 + k * 2));
            *(uint16_t*)(smem + ABUF(0) + sw) =
                __half_as_ushort(__float2half_rn(xb[xoff[i]]));
        }
    }

    // ---- per-thread GEMM/epilogue constants -----------------------------
    const int arow   = mw * 16 + (lane & 15);
    const int achunk = (lane >> 4) * 16;
    const int brow_l = ((lane >> 4) << 3) + (lane & 7);
    const int bchunk = ((lane >> 3) & 1) * 16;
    const int q      = lane & 3;                 // unit-within-pair
    const int r0     = mw * 16 + (lane >> 2);    // first owned batch row
    const int pan    = nq >> 1;                  // h panel for this quarter

    float cs[8];
#pragma unroll
    for (int m = 0; m < 8; m++) cs[m] = 0.0f;

    float* hst = (float*)(smem + OFF_HST);       // classifier staging

    __syncthreads();      // B, A-init, x_0 visible

// GEMM for tile-pair TP into bank (TP&1): 6 B-LDSM4 + 12 MMAs.
#define GEMM_TP(TP) do {                                                      \
    const int b_ = (TP) & 1;                                                  \
    d[b_][0][0] = 0.f; d[b_][0][1] = 0.f; d[b_][0][2] = 0.f; d[b_][0][3] = 0.f;\
    d[b_][1][0] = 0.f; d[b_][1][1] = 0.f; d[b_][1][2] = 0.f; d[b_][1][3] = 0.f;\
    _Pragma("unroll")                                                         \
    for (int ks = 0; ks < 6; ks++) {                                          \
        const int p  = (ks < 4) ? 0 : 1;                                      \
        const int cb = (ks < 4) ? ks * 32 : (ks - 4) * 32;                    \
        const int nb = nq * 64 + (TP) * 16;                                   \
        uint32_t bv[4];                                                       \
        LDSM4(bv[0], bv[1], bv[2], bv[3],                                     \
              sb + (p ? OFF_B1 : OFF_B0) +                                    \
              SWZ((uint32_t)((nb + brow_l) * 128 + cb + bchunk)));            \
        MMA16816(d[b_][0], av + 4 * ks, bv[0], bv[1]);                        \
        MMA16816(d[b_][1], av + 4 * ks, bv[2], bv[3]);                        \
    }                                                                         \
} while (0)

// Epilogue for tile-pair TP from bank (TP&1): LSTM pointwise, h -> abuf_w.
#define EPI_TP(TP) do {                                                       \
    const int b_ = (TP) & 1;                                                  \
    const int j = 16 * nq + 4 * (TP) + q;                                     \
    const int bytecol = pan ? (2 * j - 64) : (64 + 2 * j);                    \
    const uint32_t hdst = abuf_w + (pan ? 16384u : 0u);                       \
    _Pragma("unroll")                                                         \
    for (int rr = 0; rr < 2; rr++) {                                          \
        float gi = d[b_][0][2 * rr + 0], gf = d[b_][0][2 * rr + 1];           \
        float gg = d[b_][1][2 * rr + 0], go = d[b_][1][2 * rr + 1];           \
        float iv = sigap(gi), fv = sigap(gf);                                 \
        float gv = tanhap(gg), ov = sigap(go);                                \
        const int m = (TP) * 2 + rr;                                          \
        float c = fv * cs[m] + iv * gv;                                       \
        cs[m] = c;                                                            \
        float h = ov * tanhap(c);                                             \
        const int bb = r0 + 8 * rr;                                           \
        const uint32_t sw = SWZ((uint32_t)(bb * 128 + bytecol));              \
        *(uint16_t*)(smem + hdst + sw) = __half_as_ushort(__float2half_rn(h));\
        if (t == TSTEPS - 1) hst[bb * 65 + j] = h;                            \
    }                                                                         \
} while (0)

    for (int t = 0; t < TSTEPS; ++t) {
        const uint32_t abuf_r = (uint32_t)ABUF(t & 1);        // GEMM source
        const uint32_t abuf_w = (uint32_t)ABUF((t + 1) & 1);  // epilogue dest
        if (t) QUAD_BAR(barid);   // h_t/x_t writes to abuf_r visible

        // ---- load x_{t+1} early (latency hides under GEMM+epilogue) -----
        float xr[4];
        if (t < TSTEPS - 1) {
#pragma unroll
            for (int i = 0; i < 4; i++)
                if (xoff[i] >= 0) xr[i] = xb[xoff[i] + (t + 1) * IDIM];
        }

        // ---- A fragments for all 6 k-steps ------------------------------
        uint32_t av[24];
#pragma unroll
        for (int ks = 0; ks < 6; ks++) {
            const int p  = (ks < 4) ? 0 : 1;
            const int cb = (ks < 4) ? ks * 32 : (ks - 4) * 32;
            LDSM4(av[4 * ks], av[4 * ks + 1], av[4 * ks + 2], av[4 * ks + 3],
                  sb + abuf_r + (p ? 16384u : 0u) +
                  SWZ((uint32_t)(arow * 128 + cb + achunk)));
        }

        // ---- pipelined GEMM/epilogue over tile pairs --------------------
        float d[2][2][4];
        GEMM_TP(0);
        GEMM_TP(1); EPI_TP(0);
        GEMM_TP(2); EPI_TP(1);
        GEMM_TP(3); EPI_TP(2);
        EPI_TP(3);

        // ---- store x_{t+1} into abuf_w panel0 ---------------------------
        if (t < TSTEPS - 1) {
#pragma unroll
            for (int i = 0; i < 4; i++) {
                if (xoff[i] >= 0) {
                    int idx = ptid + i * 128;
                    int brow = idx / IDIM, k = idx % IDIM;
                    uint32_t sw = SWZ((uint32_t)((mw * 16 + brow) * 128 + k * 2));
                    *(uint16_t*)(smem + abuf_w + sw) =
                        __half_as_ushort(__float2half_rn(xr[i]));
                }
            }
        }
    }
    __syncthreads();         // all quads finished; hst complete

    // ---- classifier: out[b,cls] = b_cls + sum_j h[b,j]*Wcls[cls,j] ------
    const int bbase = blockIdx.x * BT;
    for (int idx = tid; idx < BT * 10; idx += NTHR) {
        int b = idx / 10, cls = idx % 10;
        float s = bcls[cls];
        const float* __restrict__ wc = Wcls + cls * HDIM;
#pragma unroll
        for (int j = 0; j < HDIM; j++) s += hst[b * 65 + j] * __ldg(&wc[j]);
        out[(size_t)(bbase + b) * 10 + cls] = s;
    }
}

extern "C" void kernel_launch(void* const* d_in, const int* in_sizes, int n_in,
                              void* d_out, int out_size) {
    const float* x    = (const float*)d_in[0];
    const float* Wih  = (const float*)d_in[1];
    const float* Whh  = (const float*)d_in[2];
    const float* bih  = (const float*)d_in[3];
    const float* bhh  = (const float*)d_in[4];
    const float* Wcls = (const float*)d_in[5];
    const float* bcls = (const float*)d_in[6];
    float* out = (float*)d_out;

    cudaFuncSetAttribute(lstm_mma_kernel,
                         cudaFuncAttributeMaxDynamicSharedMemorySize, SMEM_SZ);
    lstm_mma_kernel<<<16384 / BT, NTHR, SMEM_SZ>>>(x, Wih, Whh, bih, bhh,
                                                   Wcls, bcls, out);
}